// round 1
// baseline (speedup 1.0000x reference)
#include <cuda_runtime.h>
#include <cstdint>

typedef unsigned long long ull;

#define T_SEQ 1024
#define NB    8      // batches per CTA
#define NTHR  128

__device__ __forceinline__ ull pk2(float lo, float hi) {
    ull r; asm("mov.b64 %0,{%1,%2};" : "=l"(r) : "f"(lo), "f"(hi)); return r;
}
__device__ __forceinline__ void upk2(ull v, float& lo, float& hi) {
    asm("mov.b64 {%0,%1},%2;" : "=f"(lo), "=f"(hi) : "l"(v));
}
// packed dual fp32 FMA (Blackwell f32x2 pipe): d = a*b + c elementwise on 2 floats
__device__ __forceinline__ ull f2fma(ull a, ull b, ull c) {
    ull d; asm("fma.rn.f32x2 %0,%1,%2,%3;" : "=l"(d) : "l"(a), "l"(b), "l"(c)); return d;
}

__device__ __forceinline__ float sigf(float x) {
    float e = __expf(-x);                 // e >= 0, saturates safely to inf/0
    return __fdividef(1.0f, 1.0f + e);
}
__device__ __forceinline__ float tanhf_fast(float x) {
    float ax = fabsf(x);
    float e  = __expf(ax + ax);           // e >= 1; inf for large ax -> r = 1
    float r  = 1.0f - __fdividef(2.0f, e + 1.0f);
    return copysignf(r, x);
}

struct __align__(16) SMem {
    float4 xbuf[2][NB];        // double-buffered x_t per batch (4 floats)
    float  h1[NB][32];         // hidden layer1 (30 + 2 zero pad), 16B-aligned rows
    float  h2[NB][32];         // hidden layer2
    float  gates[NB][120];     // gate pre-activations (reused for both layers)
    float  wlin[4][32];        // W_lin rows padded
    float  blin[4];
};

__global__ void __launch_bounds__(NTHR, 1)
lstm2_kernel(const float* __restrict__ input,
             const float* __restrict__ Wih1, const float* __restrict__ bih1,
             const float* __restrict__ Whh1, const float* __restrict__ bhh1,
             const float* __restrict__ Wih2, const float* __restrict__ bih2,
             const float* __restrict__ Whh2, const float* __restrict__ bhh2,
             const float* __restrict__ Wlin, const float* __restrict__ blin,
             float* __restrict__ out)
{
    __shared__ SMem sm;
    const int j  = threadIdx.x;
    const int b0 = blockIdx.x * NB;

    // ---- load this thread's gate-row weights into registers (k-packed f32x2) ----
    const int jj = (j < 120) ? j : 119;   // threads 120..127 load row 119 (unused)
    ull w1[18];   // layer1: [0..1] = x pairs (4 floats), [2..17] = h1 pairs (30 + pad)
    ull w2[32];   // layer2: [0..15] = h1 pairs, [16..31] = h2 pairs
    w1[0] = pk2(Wih1[jj * 4 + 0], Wih1[jj * 4 + 1]);
    w1[1] = pk2(Wih1[jj * 4 + 2], Wih1[jj * 4 + 3]);
#pragma unroll
    for (int p = 0; p < 16; p++)
        w1[2 + p] = (p < 15) ? pk2(Whh1[jj * 30 + 2 * p], Whh1[jj * 30 + 2 * p + 1]) : 0ull;
#pragma unroll
    for (int p = 0; p < 16; p++)
        w2[p]      = (p < 15) ? pk2(Wih2[jj * 30 + 2 * p], Wih2[jj * 30 + 2 * p + 1]) : 0ull;
#pragma unroll
    for (int p = 0; p < 16; p++)
        w2[16 + p] = (p < 15) ? pk2(Whh2[jj * 30 + 2 * p], Whh2[jj * 30 + 2 * p + 1]) : 0ull;
    const ull bias1 = pk2(bih1[jj] + bhh1[jj], 0.0f);
    const ull bias2 = pk2(bih2[jj] + bhh2[jj], 0.0f);

    // ---- shared init ----
    {
        int d = j >> 5, k = j & 31;                 // 128 threads cover 4x32
        sm.wlin[d][k] = (k < 30) ? Wlin[d * 30 + k] : 0.0f;
    }
    if (j < 4) sm.blin[j] = blin[j];
    for (int idx = j; idx < NB * 32; idx += NTHR) {
        sm.h1[idx >> 5][idx & 31] = 0.0f;
        sm.h2[idx >> 5][idx & 31] = 0.0f;
    }
    if (j >= 120) {
        int i = j - 120;
        sm.xbuf[0][i] = *(const float4*)(input + ((size_t)(b0 + i) * T_SEQ) * 4);
    }
    __syncthreads();

    // activation-phase ownership: thread j -> unit u, batches {bb, bb+1}
    const int u  = (j < 120) ? (j % 30) : 0;
    const int bb = (j < 120) ? 2 * (j / 30) : 0;
    float c1s[2] = {0.0f, 0.0f};
    float c2s[2] = {0.0f, 0.0f};

    for (int t = 0; t < T_SEQ; t++) {
        // ================= phase G1: layer-1 gate pre-activations =================
        if (j < 120) {
            const int cur = t & 1;
#pragma unroll 2
            for (int b = 0; b < NB; b++) {
                ulonglong2 xv = *(const ulonglong2*)&sm.xbuf[cur][b];
                ull acc = f2fma(w1[0], xv.x, bias1);
                acc     = f2fma(w1[1], xv.y, acc);
                const ulonglong2* hp = (const ulonglong2*)sm.h1[b];
#pragma unroll
                for (int p = 0; p < 8; p++) {
                    ulonglong2 h = hp[p];
                    acc = f2fma(w1[2 + 2 * p], h.x, acc);
                    acc = f2fma(w1[3 + 2 * p], h.y, acc);
                }
                float lo, hi; upk2(acc, lo, hi);
                sm.gates[b][j] = lo + hi;
            }
        } else {
            // prefetch next x into the other buffer
            int i = j - 120, tn = t + 1;
            if (tn < T_SEQ)
                sm.xbuf[tn & 1][i] = *(const float4*)(input + ((size_t)(b0 + i) * T_SEQ + tn) * 4);
        }
        __syncthreads();

        // ================= phase A1: layer-1 cell update ==========================
        if (j < 120) {
#pragma unroll
            for (int q = 0; q < 2; q++) {
                int b = bb + q;
                float gi = sm.gates[b][u];
                float gf = sm.gates[b][u + 30];
                float gg = sm.gates[b][u + 60];
                float go = sm.gates[b][u + 90];
                float i_ = sigf(gi), f_ = sigf(gf), g_ = tanhf_fast(gg), o_ = sigf(go);
                float c  = f_ * c1s[q] + i_ * g_;
                c1s[q]   = c;
                sm.h1[b][u] = o_ * tanhf_fast(c);
            }
        }
        __syncthreads();

        // ================= phase G2: layer-2 gate pre-activations =================
        if (j < 120) {
#pragma unroll 2
            for (int b = 0; b < NB; b++) {
                ull acc = bias2;
                const ulonglong2* hp1 = (const ulonglong2*)sm.h1[b];
                const ulonglong2* hp2 = (const ulonglong2*)sm.h2[b];
#pragma unroll
                for (int p = 0; p < 8; p++) {
                    ulonglong2 h = hp1[p];
                    acc = f2fma(w2[2 * p],     h.x, acc);
                    acc = f2fma(w2[2 * p + 1], h.y, acc);
                }
#pragma unroll
                for (int p = 0; p < 8; p++) {
                    ulonglong2 h = hp2[p];
                    acc = f2fma(w2[16 + 2 * p], h.x, acc);
                    acc = f2fma(w2[17 + 2 * p], h.y, acc);
                }
                float lo, hi; upk2(acc, lo, hi);
                sm.gates[b][j] = lo + hi;
            }
        }
        __syncthreads();

        // ================= phase A2: layer-2 cell update ==========================
        if (j < 120) {
#pragma unroll
            for (int q = 0; q < 2; q++) {
                int b = bb + q;
                float gi = sm.gates[b][u];
                float gf = sm.gates[b][u + 30];
                float gg = sm.gates[b][u + 60];
                float go = sm.gates[b][u + 90];
                float i_ = sigf(gi), f_ = sigf(gf), g_ = tanhf_fast(gg), o_ = sigf(go);
                float c  = f_ * c2s[q] + i_ * g_;
                c2s[q]   = c;
                sm.h2[b][u] = o_ * tanhf_fast(c);
            }
        }
        __syncthreads();

        // ================= LIN: output projection (threads 0..31) =================
        // Safe without trailing barrier: h2 is next written at A2(t+1), which is
        // 3 barriers after every thread has passed the G1(t+1) barrier.
        if (j < 32) {
            int b = j >> 2, d = j & 3;
            float acc = sm.blin[d];
#pragma unroll
            for (int k = 0; k < 30; k++)
                acc += sm.wlin[d][k] * sm.h2[b][k];
            out[((size_t)(b0 + b) * T_SEQ + t) * 4 + d] = acc;
        }
    }
}

extern "C" void kernel_launch(void* const* d_in, const int* in_sizes, int n_in,
                              void* d_out, int out_size)
{
    const float* input = (const float*)d_in[0];
    const float* Wih1  = (const float*)d_in[1];
    const float* bih1  = (const float*)d_in[2];
    const float* Whh1  = (const float*)d_in[3];
    const float* bhh1  = (const float*)d_in[4];
    const float* Wih2  = (const float*)d_in[5];
    const float* bih2  = (const float*)d_in[6];
    const float* Whh2  = (const float*)d_in[7];
    const float* bhh2  = (const float*)d_in[8];
    const float* Wlin  = (const float*)d_in[9];
    const float* blin  = (const float*)d_in[10];
    float* out = (float*)d_out;

    int B = in_sizes[0] / (T_SEQ * 4);   // 2048
    int grid = B / NB;                   // 256 CTAs
    lstm2_kernel<<<grid, NTHR>>>(input, Wih1, bih1, Whh1, bhh1,
                                 Wih2, bih2, Whh2, bhh2, Wlin, blin, out);
}

// round 2
// speedup vs baseline: 1.1553x; 1.1553x over previous
#include <cuda_runtime.h>
#include <cstdint>

typedef unsigned long long ull;

#define T_SEQ  1024
#define NBMAX  5
#define NTHR   128

__device__ __forceinline__ ull pk2(float lo, float hi) {
    ull r; asm("mov.b64 %0,{%1,%2};" : "=l"(r) : "f"(lo), "f"(hi)); return r;
}
__device__ __forceinline__ void upk2(ull v, float& lo, float& hi) {
    asm("mov.b64 {%0,%1},%2;" : "=f"(lo), "=f"(hi) : "l"(v));
}
// packed dual fp32 FMA (Blackwell f32x2 pipe)
__device__ __forceinline__ ull f2fma(ull a, ull b, ull c) {
    ull d; asm("fma.rn.f32x2 %0,%1,%2,%3;" : "=l"(d) : "l"(a), "l"(b), "l"(c)); return d;
}

__device__ __forceinline__ float sigf(float x) {
    float e = __expf(-x);
    return __fdividef(1.0f, 1.0f + e);
}
__device__ __forceinline__ float tanhf_fast(float x) {
    float ax = fabsf(x);
    float e  = __expf(ax + ax);
    float r  = 1.0f - __fdividef(2.0f, e + 1.0f);
    return copysignf(r, x);
}

struct __align__(16) SMem {
    float4 xbuf[2][NBMAX];      // double-buffered x_t per batch
    float  h1[NBMAX][32];       // hidden layer1 (30 + 2 zero pad)
    float  h2[NBMAX][32];       // hidden layer2
    float  gates[NBMAX][120];   // gate pre-activations (reused both layers)
    float  wlin[4][32];
    float  blin[4];
};

__global__ void __launch_bounds__(NTHR, 3)
lstm2_kernel(const float* __restrict__ input,
             const float* __restrict__ Wih1, const float* __restrict__ bih1,
             const float* __restrict__ Whh1, const float* __restrict__ bhh1,
             const float* __restrict__ Wih2, const float* __restrict__ bih2,
             const float* __restrict__ Whh2, const float* __restrict__ bhh2,
             const float* __restrict__ Wlin, const float* __restrict__ blin,
             float* __restrict__ out)
{
    __shared__ SMem sm;
    const int j   = threadIdx.x;
    const int bid = blockIdx.x;

    // ---- balanced batch assignment: 444 CTAs, bids s,s+148,s+296 co-locate on
    //      one SM; per-SM nb pattern {5,5,4} (124 SMs, 14 batches) or {5,4,4}
    //      (24 SMs, 13 batches). 124*14 + 24*13 = 2048.
    const int s = bid % 148, w = bid / 148;
    int nb, b0;
    if (s < 124) { b0 = s * 14 + w * 5;                                   nb = (w < 2) ? 5 : 4; }
    else         { b0 = 124 * 14 + (s - 124) * 13 + ((w == 0) ? 0 : 5 + (w - 1) * 4);
                   nb = (w < 1) ? 5 : 4; }

    // ---- this thread's gate-row weights in registers (k-packed f32x2) ----
    const int jj = (j < 120) ? j : 119;
    ull w1[18];   // [0..1]=x pairs, [2..17]=h1 pairs (30+pad)
    ull w2[32];   // [0..15]=h1 pairs, [16..31]=h2 pairs
    w1[0] = pk2(Wih1[jj * 4 + 0], Wih1[jj * 4 + 1]);
    w1[1] = pk2(Wih1[jj * 4 + 2], Wih1[jj * 4 + 3]);
#pragma unroll
    for (int p = 0; p < 16; p++)
        w1[2 + p] = (p < 15) ? pk2(Whh1[jj * 30 + 2 * p], Whh1[jj * 30 + 2 * p + 1]) : 0ull;
#pragma unroll
    for (int p = 0; p < 16; p++)
        w2[p]      = (p < 15) ? pk2(Wih2[jj * 30 + 2 * p], Wih2[jj * 30 + 2 * p + 1]) : 0ull;
#pragma unroll
    for (int p = 0; p < 16; p++)
        w2[16 + p] = (p < 15) ? pk2(Whh2[jj * 30 + 2 * p], Whh2[jj * 30 + 2 * p + 1]) : 0ull;
    const ull bias1 = pk2(bih1[jj] + bhh1[jj], 0.0f);
    const ull bias2 = pk2(bih2[jj] + bhh2[jj], 0.0f);

    // ---- shared init ----
    {
        int d = j >> 5, k = j & 31;
        sm.wlin[d][k] = (k < 30) ? Wlin[d * 30 + k] : 0.0f;
    }
    if (j < 4) sm.blin[j] = blin[j];
    for (int idx = j; idx < NBMAX * 32; idx += NTHR) {
        sm.h1[idx >> 5][idx & 31] = 0.0f;
        sm.h2[idx >> 5][idx & 31] = 0.0f;
    }
    if (j >= 120 && (j - 120) < nb) {
        int i = j - 120;
        sm.xbuf[0][i] = *(const float4*)(input + ((size_t)(b0 + i) * T_SEQ) * 4);
    }
    __syncthreads();

    // activation ownership: thread j -> unit u, batches {slot, slot+4}
    const int u    = (j < 120) ? (j % 30) : 0;
    const int slot = (j < 120) ? (j / 30) : 0;
    float c1s[2] = {0.0f, 0.0f};
    float c2s[2] = {0.0f, 0.0f};

    for (int t = 0; t < T_SEQ; t++) {
        // ============ phase G1: layer-1 gate pre-activations ============
        if (j < 120) {
            const int cur = t & 1;
            for (int b = 0; b < nb; b++) {
                ulonglong2 xv = *(const ulonglong2*)&sm.xbuf[cur][b];
                ull acc = f2fma(w1[0], xv.x, bias1);
                acc     = f2fma(w1[1], xv.y, acc);
                const ulonglong2* hp = (const ulonglong2*)sm.h1[b];
#pragma unroll
                for (int p = 0; p < 8; p++) {
                    ulonglong2 h = hp[p];
                    acc = f2fma(w1[2 + 2 * p], h.x, acc);
                    acc = f2fma(w1[3 + 2 * p], h.y, acc);
                }
                float lo, hi; upk2(acc, lo, hi);
                sm.gates[b][j] = lo + hi;
            }
        } else {
            int i = j - 120, tn = t + 1;
            if (i < nb && tn < T_SEQ)
                sm.xbuf[tn & 1][i] = *(const float4*)(input + ((size_t)(b0 + i) * T_SEQ + tn) * 4);
        }
        __syncthreads();

        // ============ phase A1: layer-1 cell update ============
        if (j < 120) {
#pragma unroll
            for (int q = 0; q < 2; q++) {
                int b = slot + 4 * q;
                if (b < nb) {
                    float gi = sm.gates[b][u];
                    float gf = sm.gates[b][u + 30];
                    float gg = sm.gates[b][u + 60];
                    float go = sm.gates[b][u + 90];
                    float i_ = sigf(gi), f_ = sigf(gf), g_ = tanhf_fast(gg), o_ = sigf(go);
                    float c  = f_ * c1s[q] + i_ * g_;
                    c1s[q]   = c;
                    sm.h1[b][u] = o_ * tanhf_fast(c);
                }
            }
        }
        __syncthreads();

        // ============ phase G2: layer-2 gate pre-activations ============
        if (j < 120) {
            for (int b = 0; b < nb; b++) {
                ull acc = bias2;
                const ulonglong2* hp1 = (const ulonglong2*)sm.h1[b];
                const ulonglong2* hp2 = (const ulonglong2*)sm.h2[b];
#pragma unroll
                for (int p = 0; p < 8; p++) {
                    ulonglong2 h = hp1[p];
                    acc = f2fma(w2[2 * p],     h.x, acc);
                    acc = f2fma(w2[2 * p + 1], h.y, acc);
                }
#pragma unroll
                for (int p = 0; p < 8; p++) {
                    ulonglong2 h = hp2[p];
                    acc = f2fma(w2[16 + 2 * p], h.x, acc);
                    acc = f2fma(w2[17 + 2 * p], h.y, acc);
                }
                float lo, hi; upk2(acc, lo, hi);
                sm.gates[b][j] = lo + hi;
            }
        }
        __syncthreads();

        // ============ phase A2: layer-2 cell update ============
        if (j < 120) {
#pragma unroll
            for (int q = 0; q < 2; q++) {
                int b = slot + 4 * q;
                if (b < nb) {
                    float gi = sm.gates[b][u];
                    float gf = sm.gates[b][u + 30];
                    float gg = sm.gates[b][u + 60];
                    float go = sm.gates[b][u + 90];
                    float i_ = sigf(gi), f_ = sigf(gf), g_ = tanhf_fast(gg), o_ = sigf(go);
                    float c  = f_ * c2s[q] + i_ * g_;
                    c2s[q]   = c;
                    sm.h2[b][u] = o_ * tanhf_fast(c);
                }
            }
        }
        __syncthreads();

        // ============ LIN: output projection (threads 0..4*nb-1) ============
        // Safe without trailing barrier: next h2 write (A2 of t+1) is 3 barriers
        // after every thread passes the G1(t+1) barrier.
        if (j < 4 * nb) {
            int b = j >> 2, d = j & 3;
            float acc = sm.blin[d];
#pragma unroll
            for (int k = 0; k < 30; k++)
                acc += sm.wlin[d][k] * sm.h2[b][k];
            out[((size_t)(b0 + b) * T_SEQ + t) * 4 + d] = acc;
        }
    }
}

extern "C" void kernel_launch(void* const* d_in, const int* in_sizes, int n_in,
                              void* d_out, int out_size)
{
    const float* input = (const float*)d_in[0];
    const float* Wih1  = (const float*)d_in[1];
    const float* bih1  = (const float*)d_in[2];
    const float* Whh1  = (const float*)d_in[3];
    const float* bhh1  = (const float*)d_in[4];
    const float* Wih2  = (const float*)d_in[5];
    const float* bih2  = (const float*)d_in[6];
    const float* Whh2  = (const float*)d_in[7];
    const float* bhh2  = (const float*)d_in[8];
    const float* Wlin  = (const float*)d_in[9];
    const float* blin  = (const float*)d_in[10];
    float* out = (float*)d_out;

    lstm2_kernel<<<444, NTHR>>>(input, Wih1, bih1, Whh1, bhh1,
                                Wih2, bih2, Whh2, bhh2, Wlin, blin, out);
}